// round 1
// baseline (speedup 1.0000x reference)
#include <cuda_runtime.h>
#include <cuda_bf16.h>
#include <cstdint>

// ---------------- problem constants (fixed by setup_inputs) ----------------
#define NB      8
#define LQ      2500
#define DM      256
#define NH      8
#define NL      4
#define NP      8
#define NZ      4
#define DH      32
#define LEN_IN  14960
#define KDIM    256

// spatial shapes per level (h, w) and level start indices — fixed constants
__device__ __constant__ int c_H[NL]  = {64, 32, 16, 8};
__device__ __constant__ int c_W[NL]  = {176, 88, 44, 22};
__device__ __constant__ int c_ST[NL] = {0, 11264, 14080, 14784};

// ---------------- scratch (device globals; no allocation allowed) ----------
__device__ float g_value[(size_t)NB * LEN_IN * DM];          // (N, LEN_IN, NH, DH)
__device__ float g_off  [(size_t)NB * LQ * (NH * NL * NP * 2)]; // 512 per (n,q)
__device__ float g_awl  [(size_t)NB * LQ * (NH * NL * NP)];     // 256 logits per (n,q)

// ---------------- generic tiled SGEMM: C = A(MxK) @ W(KxN) + bias ----------
// K fixed at 256. BM=BN=64, BK=16, 256 threads, 4x4 microtile per thread.
__global__ void sgemm_bias_kernel(const float* __restrict__ A,
                                  const float* __restrict__ W,
                                  const float* __restrict__ bias,
                                  float* __restrict__ C,
                                  int M, int Ncols) {
    __shared__ float As[16][64];
    __shared__ float Bs[16][64];

    const int bm = blockIdx.x * 64;
    const int bn = blockIdx.y * 64;
    const int t  = threadIdx.x;           // 0..255
    const int tx = t & 15;                // 0..15 -> N microtiles
    const int ty = t >> 4;                // 0..15 -> M microtiles

    const int arow = t >> 2;              // 0..63
    const int ac4  = (t & 3) * 4;         // 0..12 (k within tile)
    const int brow = t >> 4;              // 0..15 (k within tile)
    const int bc4  = (t & 15) * 4;        // 0..60 (n within tile)

    float acc[4][4] = {};

    for (int k0 = 0; k0 < KDIM; k0 += 16) {
        float4 av;
        if (bm + arow < M) {
            av = *reinterpret_cast<const float4*>(A + (size_t)(bm + arow) * KDIM + k0 + ac4);
        } else {
            av = make_float4(0.f, 0.f, 0.f, 0.f);
        }
        As[ac4 + 0][arow] = av.x;
        As[ac4 + 1][arow] = av.y;
        As[ac4 + 2][arow] = av.z;
        As[ac4 + 3][arow] = av.w;

        float4 bv4 = *reinterpret_cast<const float4*>(W + (size_t)(k0 + brow) * Ncols + bn + bc4);
        *reinterpret_cast<float4*>(&Bs[brow][bc4]) = bv4;

        __syncthreads();

#pragma unroll
        for (int kk = 0; kk < 16; kk++) {
            float4 aq = *reinterpret_cast<const float4*>(&As[kk][ty * 4]);
            float4 bq = *reinterpret_cast<const float4*>(&Bs[kk][tx * 4]);
            float a[4] = {aq.x, aq.y, aq.z, aq.w};
            float b[4] = {bq.x, bq.y, bq.z, bq.w};
#pragma unroll
            for (int i = 0; i < 4; i++)
#pragma unroll
                for (int j = 0; j < 4; j++)
                    acc[i][j] += a[i] * b[j];
        }
        __syncthreads();
    }

#pragma unroll
    for (int i = 0; i < 4; i++) {
        int row = bm + ty * 4 + i;
        if (row < M) {
#pragma unroll
            for (int j = 0; j < 4; j++) {
                int col = bn + tx * 4 + j;
                C[(size_t)row * Ncols + col] = acc[i][j] + bias[col];
            }
        }
    }
}

// ---------------- deformable sampling + softmax + weighted accumulation ----
// grid: N*LQ blocks; block: 256 threads = 8 warps (one per head); lane = channel.
__global__ void msda_sample_kernel(const float* __restrict__ ref,   // (N,LQ,NZ,2)
                                   const float* __restrict__ off,   // (N,LQ,NH,NL,NP,2)
                                   const float* __restrict__ awl,   // (N,LQ,NH,NL*NP) logits
                                   const float* __restrict__ value, // (N,LEN_IN,NH,DH)
                                   float* __restrict__ out)         // (N,LQ,NH,DH)
{
    const int nq   = blockIdx.x;            // n*LQ + q
    const int n    = nq / LQ;
    const int h    = threadIdx.x >> 5;
    const int lane = threadIdx.x & 31;

    // per-lane sample state: lane j holds (offx, offy, weight) for sample j
    const float* offp = off + ((size_t)nq * NH + h) * (NL * NP * 2);
    float offx = offp[2 * lane + 0];
    float offy = offp[2 * lane + 1];

    // softmax over the 32 logits of this head (one logit per lane)
    float logit = awl[((size_t)nq * NH + h) * (NL * NP) + lane];
    float m = logit;
#pragma unroll
    for (int s = 16; s > 0; s >>= 1) m = fmaxf(m, __shfl_xor_sync(0xffffffffu, m, s));
    float e = expf(logit - m);
    float ssum = e;
#pragma unroll
    for (int s = 16; s > 0; s >>= 1) ssum += __shfl_xor_sync(0xffffffffu, ssum, s);
    float wgt = e / ssum;

    const float* refp  = ref + (size_t)nq * NZ * 2;
    const float* vbase = value + ((size_t)n * LEN_IN * NH + h) * DH + lane;

    float acc = 0.f;

#pragma unroll
    for (int l = 0; l < NL; l++) {
        const int   hl = c_H[l];
        const int   wl = c_W[l];
        const int   st = c_ST[l];
        const float fhl = (float)hl;
        const float fwl = (float)wl;
#pragma unroll
        for (int p = 0; p < NP; p++) {
            const int j = l * NP + p;
            const float ox = __shfl_sync(0xffffffffu, offx, j);
            const float oy = __shfl_sync(0xffffffffu, offy, j);
            const float wj = __shfl_sync(0xffffffffu, wgt,  j);
            const int z = p & (NZ - 1);
            const float rx = refp[2 * z + 0];   // broadcast load
            const float ry = refp[2 * z + 1];

            // loc = ref + off / (w, h);  x = loc.x * w - 0.5, y = loc.y * h - 0.5
            const float locx = rx + ox / fwl;
            const float locy = ry + oy / fhl;
            const float x = locx * fwl - 0.5f;
            const float y = locy * fhl - 0.5f;

            const float x0f = floorf(x);
            const float y0f = floorf(y);
            const float wx = x - x0f;
            const float wy = y - y0f;
            const int x0 = (int)x0f;
            const int y0 = (int)y0f;
            const int x1 = x0 + 1;
            const int y1 = y0 + 1;

            const float w00 = (1.f - wx) * (1.f - wy);
            const float w10 = wx * (1.f - wy);
            const float w01 = (1.f - wx) * wy;
            const float w11 = wx * wy;

            const bool vx0 = (x0 >= 0) && (x0 < wl);
            const bool vx1 = (x1 >= 0) && (x1 < wl);
            const bool vy0 = (y0 >= 0) && (y0 < hl);
            const bool vy1 = (y1 >= 0) && (y1 < hl);

            if (vy0) {
                const size_t rowb = (size_t)(st + y0 * wl) * (NH * DH);
                if (vx0) acc += wj * w00 * vbase[rowb + (size_t)x0 * (NH * DH)];
                if (vx1) acc += wj * w10 * vbase[rowb + (size_t)x1 * (NH * DH)];
            }
            if (vy1) {
                const size_t rowb = (size_t)(st + y1 * wl) * (NH * DH);
                if (vx0) acc += wj * w01 * vbase[rowb + (size_t)x0 * (NH * DH)];
                if (vx1) acc += wj * w11 * vbase[rowb + (size_t)x1 * (NH * DH)];
            }
        }
    }

    out[((size_t)nq * NH + h) * DH + lane] = acc;
}

// ---------------- launch ----------------------------------------------------
extern "C" void kernel_launch(void* const* d_in, const int* in_sizes, int n_in,
                              void* d_out, int out_size) {
    const float* query  = (const float*)d_in[0];   // (8,2500,256)
    // d_in[1] = query_pos (unused by the reference forward)
    const float* refpts = (const float*)d_in[2];   // (8,2500,4,2)
    const float* inflat = (const float*)d_in[3];   // (8,14960,256)
    // d_in[4] = input_spatial_shapes, d_in[5] = level_start_index (compile-time constants)
    const float* Wv = (const float*)d_in[6];       // (256,256)
    const float* bv = (const float*)d_in[7];       // (256,)
    const float* Wo = (const float*)d_in[8];       // (256,512)
    const float* bo = (const float*)d_in[9];       // (512,)
    const float* Wa = (const float*)d_in[10];      // (256,256)
    const float* ba = (const float*)d_in[11];      // (256,)
    float* out = (float*)d_out;

    float *valuep, *offp, *awlp;
    cudaGetSymbolAddress((void**)&valuep, g_value);
    cudaGetSymbolAddress((void**)&offp,   g_off);
    cudaGetSymbolAddress((void**)&awlp,   g_awl);

    const int Mv = NB * LEN_IN;    // 119680
    const int Mq = NB * LQ;        // 20000

    // value = input_flatten @ Wv + bv  : (119680,256)@(256,256)
    {
        dim3 grid(Mv / 64, DM / 64);
        sgemm_bias_kernel<<<grid, 256>>>(inflat, Wv, bv, valuep, Mv, DM);
    }
    // off = query @ Wo + bo : (20000,256)@(256,512)
    {
        dim3 grid((Mq + 63) / 64, 512 / 64);
        sgemm_bias_kernel<<<grid, 256>>>(query, Wo, bo, offp, Mq, 512);
    }
    // aw logits = query @ Wa + ba : (20000,256)@(256,256)
    {
        dim3 grid((Mq + 63) / 64, 256 / 64);
        sgemm_bias_kernel<<<grid, 256>>>(query, Wa, ba, awlp, Mq, 256);
    }
    // sampling + softmax + weighted accumulation
    msda_sample_kernel<<<Mq, 256>>>(refpts, offp, awlp, valuep, out);
}

// round 2
// speedup vs baseline: 1.7961x; 1.7961x over previous
#include <cuda_runtime.h>
#include <cuda_bf16.h>
#include <cstdint>

// ---------------- problem constants (fixed by setup_inputs) ----------------
#define NB      8
#define LQ      2500
#define DM      256
#define NH      8
#define NL      4
#define NP      8
#define NZ      4
#define DH      32
#define LEN_IN  14960
#define KDIM    256

__device__ __constant__ int c_H[NL]  = {64, 32, 16, 8};
__device__ __constant__ int c_W[NL]  = {176, 88, 44, 22};
__device__ __constant__ int c_ST[NL] = {0, 11264, 14080, 14784};

// ---------------- scratch ----------
__device__ float g_value[(size_t)NB * LEN_IN * DM];             // (N, LEN_IN, NH, DH)
__device__ float g_off  [(size_t)NB * LQ * (NH * NL * NP * 2)]; // 512 per (n,q)
__device__ float g_awl  [(size_t)NB * LQ * (NH * NL * NP)];     // 256 logits per (n,q)

// =====================================================================
// Split-bf16 (bf16x3) tensor-core GEMM:  C = A(MxK) @ W(KxN) + bias
// K = 256 fixed. BM=128, BN=64, BK=32. 256 threads = 8 warps (4M x 2N),
// warp tile 32x32, mma.m16n8k16.bf16, 3 accumulation terms:
//   hi*hi + hi*lo + lo*hi  (error ~2^-17 per product -> fp32-class result)
// =====================================================================
#define GBM 128
#define GBN 64
#define GBK 32
#define GPAD 2

__device__ __forceinline__ void split_bf16(float f, __nv_bfloat16& h, __nv_bfloat16& l) {
    h = __float2bfloat16(f);
    l = __float2bfloat16(f - __bfloat162float(h));
}

__device__ __forceinline__ void mma16816(float c[4], uint32_t a0, uint32_t a1,
                                         uint32_t a2, uint32_t a3,
                                         uint32_t b0, uint32_t b1) {
    asm volatile(
        "mma.sync.aligned.m16n8k16.row.col.f32.bf16.bf16.f32 "
        "{%0,%1,%2,%3}, {%4,%5,%6,%7}, {%8,%9}, {%0,%1,%2,%3};"
        : "+f"(c[0]), "+f"(c[1]), "+f"(c[2]), "+f"(c[3])
        : "r"(a0), "r"(a1), "r"(a2), "r"(a3), "r"(b0), "r"(b1));
}

__global__ __launch_bounds__(256, 2)
void gemm_bf16x3_kernel(const float* __restrict__ A,
                        const float* __restrict__ W,
                        const float* __restrict__ bias,
                        float* __restrict__ C,
                        int M, int N) {
    __shared__ __nv_bfloat16 Ah[GBM][GBK + GPAD];
    __shared__ __nv_bfloat16 Al[GBM][GBK + GPAD];
    __shared__ __nv_bfloat16 Bh[GBN][GBK + GPAD];   // transposed: [n][k]
    __shared__ __nv_bfloat16 Bl[GBN][GBK + GPAD];

    const int bm = blockIdx.x * GBM;
    const int bn = blockIdx.y * GBN;
    const int t  = threadIdx.x;
    const int lane = t & 31;
    const int wid  = t >> 5;
    const int warpM = (wid & 3) * 32;   // 4 warps along M
    const int warpN = (wid >> 2) * 32;  // 2 warps along N
    const int gr = lane >> 2;           // 0..7
    const int kq = (lane & 3) * 2;      // 0,2,4,6

    // A loader: r = t>>1 (0..127), seg = (t&1)*16 ; 4 x float4
    const int a_r   = t >> 1;
    const int a_seg = (t & 1) * 16;
    // B loader: krow = t>>3 (0..31), cseg = (t&7)*8 ; 2 x float4
    const int b_kr = t >> 3;
    const int b_cs = (t & 7) * 8;

    float acc[2][4][4];
#pragma unroll
    for (int i = 0; i < 2; i++)
#pragma unroll
        for (int j = 0; j < 4; j++)
#pragma unroll
            for (int k = 0; k < 4; k++) acc[i][j][k] = 0.f;

    const bool a_valid = (bm + a_r) < M;

    for (int k0 = 0; k0 < KDIM; k0 += GBK) {
        // ---- load A tile (128x32 fp32), split to bf16 hi/lo ----
#pragma unroll
        for (int i = 0; i < 4; i++) {
            float4 v = make_float4(0.f, 0.f, 0.f, 0.f);
            if (a_valid)
                v = *reinterpret_cast<const float4*>(
                    A + (size_t)(bm + a_r) * KDIM + k0 + a_seg + i * 4);
            __nv_bfloat16 h0, l0, h1, l1, h2, l2, h3, l3;
            split_bf16(v.x, h0, l0); split_bf16(v.y, h1, l1);
            split_bf16(v.z, h2, l2); split_bf16(v.w, h3, l3);
            const int c0 = a_seg + i * 4;
            Ah[a_r][c0 + 0] = h0; Al[a_r][c0 + 0] = l0;
            Ah[a_r][c0 + 1] = h1; Al[a_r][c0 + 1] = l1;
            Ah[a_r][c0 + 2] = h2; Al[a_r][c0 + 2] = l2;
            Ah[a_r][c0 + 3] = h3; Al[a_r][c0 + 3] = l3;
        }
        // ---- load B tile (32x64 fp32), split, store transposed [n][k] ----
#pragma unroll
        for (int i = 0; i < 2; i++) {
            float4 v = *reinterpret_cast<const float4*>(
                W + (size_t)(k0 + b_kr) * N + bn + b_cs + i * 4);
            __nv_bfloat16 h, l;
            split_bf16(v.x, h, l); Bh[b_cs + i*4 + 0][b_kr] = h; Bl[b_cs + i*4 + 0][b_kr] = l;
            split_bf16(v.y, h, l); Bh[b_cs + i*4 + 1][b_kr] = h; Bl[b_cs + i*4 + 1][b_kr] = l;
            split_bf16(v.z, h, l); Bh[b_cs + i*4 + 2][b_kr] = h; Bl[b_cs + i*4 + 2][b_kr] = l;
            split_bf16(v.w, h, l); Bh[b_cs + i*4 + 3][b_kr] = h; Bl[b_cs + i*4 + 3][b_kr] = l;
        }
        __syncthreads();

#pragma unroll
        for (int ks = 0; ks < GBK; ks += 16) {
            uint32_t ahi[2][4], alo[2][4], bhi[4][2], blo[4][2];
#pragma unroll
            for (int mt = 0; mt < 2; mt++) {
                const int r0 = warpM + mt * 16 + gr;
                ahi[mt][0] = *reinterpret_cast<const uint32_t*>(&Ah[r0    ][ks + kq    ]);
                ahi[mt][1] = *reinterpret_cast<const uint32_t*>(&Ah[r0 + 8][ks + kq    ]);
                ahi[mt][2] = *reinterpret_cast<const uint32_t*>(&Ah[r0    ][ks + kq + 8]);
                ahi[mt][3] = *reinterpret_cast<const uint32_t*>(&Ah[r0 + 8][ks + kq + 8]);
                alo[mt][0] = *reinterpret_cast<const uint32_t*>(&Al[r0    ][ks + kq    ]);
                alo[mt][1] = *reinterpret_cast<const uint32_t*>(&Al[r0 + 8][ks + kq    ]);
                alo[mt][2] = *reinterpret_cast<const uint32_t*>(&Al[r0    ][ks + kq + 8]);
                alo[mt][3] = *reinterpret_cast<const uint32_t*>(&Al[r0 + 8][ks + kq + 8]);
            }
#pragma unroll
            for (int nt = 0; nt < 4; nt++) {
                const int cN = warpN + nt * 8 + gr;
                bhi[nt][0] = *reinterpret_cast<const uint32_t*>(&Bh[cN][ks + kq    ]);
                bhi[nt][1] = *reinterpret_cast<const uint32_t*>(&Bh[cN][ks + kq + 8]);
                blo[nt][0] = *reinterpret_cast<const uint32_t*>(&Bl[cN][ks + kq    ]);
                blo[nt][1] = *reinterpret_cast<const uint32_t*>(&Bl[cN][ks + kq + 8]);
            }
#pragma unroll
            for (int mt = 0; mt < 2; mt++)
#pragma unroll
                for (int nt = 0; nt < 4; nt++) {
                    mma16816(acc[mt][nt], ahi[mt][0], ahi[mt][1], ahi[mt][2], ahi[mt][3],
                             bhi[nt][0], bhi[nt][1]);
                    mma16816(acc[mt][nt], ahi[mt][0], ahi[mt][1], ahi[mt][2], ahi[mt][3],
                             blo[nt][0], blo[nt][1]);
                    mma16816(acc[mt][nt], alo[mt][0], alo[mt][1], alo[mt][2], alo[mt][3],
                             bhi[nt][0], bhi[nt][1]);
                }
        }
        __syncthreads();
    }

    // ---- epilogue: C[row][col..col+1] = acc + bias ----
#pragma unroll
    for (int mt = 0; mt < 2; mt++) {
#pragma unroll
        for (int nt = 0; nt < 4; nt++) {
            const int col = bn + warpN + nt * 8 + kq;
            const float2 bb = *reinterpret_cast<const float2*>(&bias[col]);
            const int r0 = bm + warpM + mt * 16 + gr;
            if (r0 < M) {
                float2 o; o.x = acc[mt][nt][0] + bb.x; o.y = acc[mt][nt][1] + bb.y;
                *reinterpret_cast<float2*>(&C[(size_t)r0 * N + col]) = o;
            }
            if (r0 + 8 < M) {
                float2 o; o.x = acc[mt][nt][2] + bb.x; o.y = acc[mt][nt][3] + bb.y;
                *reinterpret_cast<float2*>(&C[(size_t)(r0 + 8) * N + col]) = o;
            }
        }
    }
}

// =====================================================================
// Sampling: phase 1 (thread = (head,sample)) computes 4 addresses +
// 4 softmax-folded corner weights into smem; phase 2 (warp = head,
// lane = channel) does pure gather+FMA with zero predication.
// =====================================================================
__global__ __launch_bounds__(256)
void msda_sample_kernel(const float* __restrict__ ref,   // (N,LQ,NZ,2)
                        const float* __restrict__ off,   // (N,LQ,NH,NL,NP,2)
                        const float* __restrict__ awl,   // (N,LQ,NH,32) logits
                        const float* __restrict__ value, // (N,LEN_IN,NH,DH)
                        float* __restrict__ out)         // (N,LQ,NH,DH)
{
    __shared__ int4   s_addr[NH * 32];
    __shared__ float4 s_w[NH * 32];

    const int nq   = blockIdx.x;
    const int n    = nq / LQ;
    const int t    = threadIdx.x;
    const int h    = t >> 5;
    const int j    = t & 31;   // sample index in phase 1, channel in phase 2

    // ---------------- phase 1 ----------------
    {
        const float logit = awl[((size_t)nq * NH + h) * 32 + j];
        float m = logit;
#pragma unroll
        for (int s = 16; s > 0; s >>= 1) m = fmaxf(m, __shfl_xor_sync(0xffffffffu, m, s));
        const float e = __expf(logit - m);
        float ssum = e;
#pragma unroll
        for (int s = 16; s > 0; s >>= 1) ssum += __shfl_xor_sync(0xffffffffu, ssum, s);
        const float wgt = e / ssum;

        const float ox = off[(((size_t)nq * NH + h) * 32 + j) * 2 + 0];
        const float oy = off[(((size_t)nq * NH + h) * 32 + j) * 2 + 1];

        const int l = j >> 3;
        const int z = j & 3;
        const float rx = ref[((size_t)nq * NZ + z) * 2 + 0];
        const float ry = ref[((size_t)nq * NZ + z) * 2 + 1];

        const int   hl = c_H[l];
        const int   wl = c_W[l];
        const int   st = c_ST[l];
        const float fhl = (float)hl;
        const float fwl = (float)wl;

        const float x = (rx + __fdividef(ox, fwl)) * fwl - 0.5f;
        const float y = (ry + __fdividef(oy, fhl)) * fhl - 0.5f;

        const float x0f = floorf(x);
        const float y0f = floorf(y);
        const float wx = x - x0f;
        const float wy = y - y0f;
        const int x0 = (int)x0f, y0 = (int)y0f;
        const int x1 = x0 + 1,   y1 = y0 + 1;

        const bool vx0 = (x0 >= 0) & (x0 < wl);
        const bool vx1 = (x1 >= 0) & (x1 < wl);
        const bool vy0 = (y0 >= 0) & (y0 < hl);
        const bool vy1 = (y1 >= 0) & (y1 < hl);

        const bool v00 = vx0 & vy0, v10 = vx1 & vy0;
        const bool v01 = vx0 & vy1, v11 = vx1 & vy1;

        int4 a;
        a.x = v00 ? (st + y0 * wl + x0) * DM : 0;
        a.y = v10 ? (st + y0 * wl + x1) * DM : 0;
        a.z = v01 ? (st + y1 * wl + x0) * DM : 0;
        a.w = v11 ? (st + y1 * wl + x1) * DM : 0;

        float4 w4;
        w4.x = v00 ? wgt * (1.f - wx) * (1.f - wy) : 0.f;
        w4.y = v10 ? wgt * wx * (1.f - wy)         : 0.f;
        w4.z = v01 ? wgt * (1.f - wx) * wy         : 0.f;
        w4.w = v11 ? wgt * wx * wy                 : 0.f;

        s_addr[t] = a;
        s_w[t]    = w4;
    }
    __syncthreads();

    // ---------------- phase 2 ----------------
    const float* __restrict__ vb =
        value + (size_t)n * LEN_IN * DM + h * DH + j;   // j == channel lane

    float acc = 0.f;
#pragma unroll 8
    for (int s = 0; s < 32; s++) {
        const int4   a  = s_addr[h * 32 + s];
        const float4 w4 = s_w[h * 32 + s];
        acc += w4.x * __ldg(vb + a.x);
        acc += w4.y * __ldg(vb + a.y);
        acc += w4.z * __ldg(vb + a.z);
        acc += w4.w * __ldg(vb + a.w);
    }

    out[(size_t)nq * DM + h * DH + j] = acc;
}

// ---------------- launch ----------------------------------------------------
extern "C" void kernel_launch(void* const* d_in, const int* in_sizes, int n_in,
                              void* d_out, int out_size) {
    const float* query  = (const float*)d_in[0];   // (8,2500,256)
    const float* refpts = (const float*)d_in[2];   // (8,2500,4,2)
    const float* inflat = (const float*)d_in[3];   // (8,14960,256)
    const float* Wv = (const float*)d_in[6];       // (256,256)
    const float* bv = (const float*)d_in[7];
    const float* Wo = (const float*)d_in[8];       // (256,512)
    const float* bo = (const float*)d_in[9];
    const float* Wa = (const float*)d_in[10];      // (256,256)
    const float* ba = (const float*)d_in[11];
    float* out = (float*)d_out;

    float *valuep, *offp, *awlp;
    cudaGetSymbolAddress((void**)&valuep, g_value);
    cudaGetSymbolAddress((void**)&offp,   g_off);
    cudaGetSymbolAddress((void**)&awlp,   g_awl);

    const int Mv = NB * LEN_IN;    // 119680
    const int Mq = NB * LQ;        // 20000

    {   // value = input_flatten @ Wv + bv : (119680,256)@(256,256)
        dim3 grid(Mv / GBM, DM / GBN);
        gemm_bf16x3_kernel<<<grid, 256>>>(inflat, Wv, bv, valuep, Mv, DM);
    }
    {   // off = query @ Wo + bo : (20000,256)@(256,512)
        dim3 grid((Mq + GBM - 1) / GBM, 512 / GBN);
        gemm_bf16x3_kernel<<<grid, 256>>>(query, Wo, bo, offp, Mq, 512);
    }
    {   // aw logits = query @ Wa + ba : (20000,256)@(256,256)
        dim3 grid((Mq + GBM - 1) / GBM, 256 / GBN);
        gemm_bf16x3_kernel<<<grid, 256>>>(query, Wa, ba, awlp, Mq, 256);
    }
    msda_sample_kernel<<<Mq, 256>>>(refpts, offp, awlp, valuep, out);
}

// round 3
// speedup vs baseline: 2.4782x; 1.3798x over previous
#include <cuda_runtime.h>
#include <cuda_bf16.h>
#include <cstdint>

// ---------------- problem constants ----------------
#define NB      8
#define LQ      2500
#define DM      256
#define NH      8
#define NL      4
#define NP      8
#define NZ      4
#define DH      32
#define LEN_IN  14960
#define KDIM    256

__device__ __constant__ int c_H[NL]  = {64, 32, 16, 8};
__device__ __constant__ int c_W[NL]  = {176, 88, 44, 22};
__device__ __constant__ int c_ST[NL] = {0, 11264, 14080, 14784};

// ---------------- scratch ----------
__device__ float g_value[(size_t)NB * LEN_IN * DM];
__device__ float g_off  [(size_t)NB * LQ * 512];
__device__ float g_awl  [(size_t)NB * LQ * 256];

__device__ __nv_bfloat16 g_vhi[(size_t)NB * LEN_IN * KDIM];
__device__ __nv_bfloat16 g_vlo[(size_t)NB * LEN_IN * KDIM];
__device__ __nv_bfloat16 g_qhi[(size_t)NB * LQ * KDIM];
__device__ __nv_bfloat16 g_qlo[(size_t)NB * LQ * KDIM];
__device__ __nv_bfloat16 g_wvhi[KDIM * 256], g_wvlo[KDIM * 256];
__device__ __nv_bfloat16 g_wohi[KDIM * 512], g_wolo[KDIM * 512];
__device__ __nv_bfloat16 g_wahi[KDIM * 256], g_walo[KDIM * 256];

// =====================================================================
// Split pass: fp32 -> bf16 hi + bf16 lo (residual)
// =====================================================================
__global__ void split_kernel(const float* __restrict__ src,
                             __nv_bfloat16* __restrict__ hi,
                             __nv_bfloat16* __restrict__ lo, int n4) {
    int i = blockIdx.x * blockDim.x + threadIdx.x;
    if (i >= n4) return;
    float4 v = reinterpret_cast<const float4*>(src)[i];
    __nv_bfloat16 h0 = __float2bfloat16(v.x);
    __nv_bfloat16 h1 = __float2bfloat16(v.y);
    __nv_bfloat16 h2 = __float2bfloat16(v.z);
    __nv_bfloat16 h3 = __float2bfloat16(v.w);
    __nv_bfloat16 l0 = __float2bfloat16(v.x - __bfloat162float(h0));
    __nv_bfloat16 l1 = __float2bfloat16(v.y - __bfloat162float(h1));
    __nv_bfloat16 l2 = __float2bfloat16(v.z - __bfloat162float(h2));
    __nv_bfloat16 l3 = __float2bfloat16(v.w - __bfloat162float(h3));
    ushort4 hu = make_ushort4(*reinterpret_cast<unsigned short*>(&h0),
                              *reinterpret_cast<unsigned short*>(&h1),
                              *reinterpret_cast<unsigned short*>(&h2),
                              *reinterpret_cast<unsigned short*>(&h3));
    ushort4 lu = make_ushort4(*reinterpret_cast<unsigned short*>(&l0),
                              *reinterpret_cast<unsigned short*>(&l1),
                              *reinterpret_cast<unsigned short*>(&l2),
                              *reinterpret_cast<unsigned short*>(&l3));
    reinterpret_cast<ushort4*>(hi)[i] = hu;
    reinterpret_cast<ushort4*>(lo)[i] = lu;
}

// =====================================================================
// bf16x3 GEMM with cp.async double buffering + ldmatrix
// C(MxN) = Ahi@Bhi + Ahi@Blo + Alo@Bhi + bias ;  K = 256
// BM=128 BN=64 BK=32, 256 threads = 8 warps (4M x 2N), warp tile 32x32
// =====================================================================
#define BM 128
#define BN 64
#define BK 32
#define AP 40          // A smem pitch in elems (80 B, 16B-multiple, conflict-free)
#define BP 72          // B smem pitch in elems (144 B)
#define OFF_AH 0
#define OFF_AL 10240   // 2*128*40
#define OFF_BH 20480
#define OFF_BL 25088   // + 2*32*72
#define SMEM_BYTES (29696 * 2)

__device__ __forceinline__ void cp16(uint32_t dst, const void* src, bool v) {
    asm volatile("cp.async.ca.shared.global [%0], [%1], 16, %2;\n"
                 :: "r"(dst), "l"(src), "r"(v ? 16 : 0));
}
__device__ __forceinline__ void ldsm4(uint32_t r[4], uint32_t a) {
    asm volatile("ldmatrix.sync.aligned.m8n8.x4.shared.b16 {%0,%1,%2,%3}, [%4];"
                 : "=r"(r[0]), "=r"(r[1]), "=r"(r[2]), "=r"(r[3]) : "r"(a));
}
__device__ __forceinline__ void ldsm4t(uint32_t r[4], uint32_t a) {
    asm volatile("ldmatrix.sync.aligned.m8n8.x4.trans.shared.b16 {%0,%1,%2,%3}, [%4];"
                 : "=r"(r[0]), "=r"(r[1]), "=r"(r[2]), "=r"(r[3]) : "r"(a));
}
__device__ __forceinline__ void mma16816(float c[4], const uint32_t a[4],
                                         uint32_t b0, uint32_t b1) {
    asm volatile(
        "mma.sync.aligned.m16n8k16.row.col.f32.bf16.bf16.f32 "
        "{%0,%1,%2,%3}, {%4,%5,%6,%7}, {%8,%9}, {%0,%1,%2,%3};"
        : "+f"(c[0]), "+f"(c[1]), "+f"(c[2]), "+f"(c[3])
        : "r"(a[0]), "r"(a[1]), "r"(a[2]), "r"(a[3]), "r"(b0), "r"(b1));
}

__global__ __launch_bounds__(256)
void gemm_split3_kernel(const __nv_bfloat16* __restrict__ Ahi,
                        const __nv_bfloat16* __restrict__ Alo,
                        const __nv_bfloat16* __restrict__ Bhi,
                        const __nv_bfloat16* __restrict__ Blo,
                        const float* __restrict__ bias,
                        float* __restrict__ C, int M, int N) {
    extern __shared__ __nv_bfloat16 sm[];
    const uint32_t smb = (uint32_t)__cvta_generic_to_shared(sm);

    const int bn = blockIdx.x * BN;      // bn fastest -> A slab shared in L2
    const int bm = blockIdx.y * BM;
    const int t = threadIdx.x, lane = t & 31, wid = t >> 5;
    const int wM = (wid & 3) * 32, wN = (wid >> 2) * 32;

    // loader mapping
    const int a_row = t >> 1;            // 0..127
    const int a_seg = (t & 1) * 2;       // chunk segs {0,1} or {2,3}
    const bool a_v  = (bm + a_row) < M;
    const size_t a_rowoff = (size_t)(a_v ? bm + a_row : 0) * KDIM;
    const int b_row = t >> 3;            // 0..31 (k)
    const int b_seg = t & 7;             // 0..7  (n chunk)

    float acc[2][4][4];
#pragma unroll
    for (int i = 0; i < 2; i++)
#pragma unroll
        for (int j = 0; j < 4; j++)
#pragma unroll
            for (int k = 0; k < 4; k++) acc[i][j][k] = 0.f;

    auto load_stage = [&](int s, int k0) {
        const uint32_t ah = smb + (uint32_t)(OFF_AH + s * 5120 + a_row * AP) * 2;
        const uint32_t al = smb + (uint32_t)(OFF_AL + s * 5120 + a_row * AP) * 2;
        cp16(ah + (a_seg + 0) * 16, Ahi + a_rowoff + k0 + (a_seg + 0) * 8, a_v);
        cp16(ah + (a_seg + 1) * 16, Ahi + a_rowoff + k0 + (a_seg + 1) * 8, a_v);
        cp16(al + (a_seg + 0) * 16, Alo + a_rowoff + k0 + (a_seg + 0) * 8, a_v);
        cp16(al + (a_seg + 1) * 16, Alo + a_rowoff + k0 + (a_seg + 1) * 8, a_v);
        const size_t bs = (size_t)(k0 + b_row) * N + bn + b_seg * 8;
        cp16(smb + (uint32_t)(OFF_BH + s * 2304 + b_row * BP + b_seg * 8) * 2, Bhi + bs, true);
        cp16(smb + (uint32_t)(OFF_BL + s * 2304 + b_row * BP + b_seg * 8) * 2, Blo + bs, true);
    };

    load_stage(0, 0);
    asm volatile("cp.async.commit_group;\n");
    load_stage(1, BK);
    asm volatile("cp.async.commit_group;\n");

    const int NIT = KDIM / BK;   // 8
#pragma unroll
    for (int it = 0; it < NIT; it++) {
        if (it < NIT - 1) asm volatile("cp.async.wait_group 1;\n");
        else              asm volatile("cp.async.wait_group 0;\n");
        __syncthreads();

        const int s = it & 1;
        const uint32_t abaseH = smb + (uint32_t)(OFF_AH + s * 5120) * 2;
        const uint32_t abaseL = smb + (uint32_t)(OFF_AL + s * 5120) * 2;
        const uint32_t bbaseH = smb + (uint32_t)(OFF_BH + s * 2304) * 2;
        const uint32_t bbaseL = smb + (uint32_t)(OFF_BL + s * 2304) * 2;

#pragma unroll
        for (int ks = 0; ks < BK; ks += 16) {
            uint32_t ah[2][4], al[2][4], bh[4][2], bl[4][2];
#pragma unroll
            for (int mt = 0; mt < 2; mt++) {
                const int r = wM + mt * 16 + (lane & 15);
                const int c = ks + (lane >> 4) * 8;
                ldsm4(ah[mt], abaseH + (uint32_t)(r * AP + c) * 2);
                ldsm4(al[mt], abaseL + (uint32_t)(r * AP + c) * 2);
            }
#pragma unroll
            for (int g = 0; g < 2; g++) {
                const int r = ks + (lane & 15);
                const int c = wN + g * 16 + (lane >> 4) * 8;
                uint32_t rb[4];
                ldsm4t(rb, bbaseH + (uint32_t)(r * BP + c) * 2);
                bh[g*2+0][0] = rb[0]; bh[g*2+0][1] = rb[1];
                bh[g*2+1][0] = rb[2]; bh[g*2+1][1] = rb[3];
                ldsm4t(rb, bbaseL + (uint32_t)(r * BP + c) * 2);
                bl[g*2+0][0] = rb[0]; bl[g*2+0][1] = rb[1];
                bl[g*2+1][0] = rb[2]; bl[g*2+1][1] = rb[3];
            }
#pragma unroll
            for (int mt = 0; mt < 2; mt++)
#pragma unroll
                for (int nt = 0; nt < 4; nt++) {
                    mma16816(acc[mt][nt], ah[mt], bh[nt][0], bh[nt][1]);
                    mma16816(acc[mt][nt], ah[mt], bl[nt][0], bl[nt][1]);
                    mma16816(acc[mt][nt], al[mt], bh[nt][0], bh[nt][1]);
                }
        }
        __syncthreads();
        if (it + 2 < NIT) {
            load_stage(s, (it + 2) * BK);
            asm volatile("cp.async.commit_group;\n");
        }
    }

    // epilogue
    const int gr = lane >> 2;
    const int kq = (lane & 3) * 2;
#pragma unroll
    for (int mt = 0; mt < 2; mt++) {
#pragma unroll
        for (int nt = 0; nt < 4; nt++) {
            const int col = bn + wN + nt * 8 + kq;
            const float2 bb = *reinterpret_cast<const float2*>(&bias[col]);
            const int r0 = bm + wM + mt * 16 + gr;
            if (r0 < M) {
                float2 o; o.x = acc[mt][nt][0] + bb.x; o.y = acc[mt][nt][1] + bb.y;
                *reinterpret_cast<float2*>(&C[(size_t)r0 * N + col]) = o;
            }
            if (r0 + 8 < M) {
                float2 o; o.x = acc[mt][nt][2] + bb.x; o.y = acc[mt][nt][3] + bb.y;
                *reinterpret_cast<float2*>(&C[(size_t)(r0 + 8) * N + col]) = o;
            }
        }
    }
}

// =====================================================================
// Sampling kernel (unchanged from R2)
// =====================================================================
__global__ __launch_bounds__(256)
void msda_sample_kernel(const float* __restrict__ ref,
                        const float* __restrict__ off,
                        const float* __restrict__ awl,
                        const float* __restrict__ value,
                        float* __restrict__ out)
{
    __shared__ int4   s_addr[NH * 32];
    __shared__ float4 s_w[NH * 32];

    const int nq = blockIdx.x;
    const int n  = nq / LQ;
    const int t  = threadIdx.x;
    const int h  = t >> 5;
    const int j  = t & 31;

    {
        const float logit = awl[((size_t)nq * NH + h) * 32 + j];
        float m = logit;
#pragma unroll
        for (int s = 16; s > 0; s >>= 1) m = fmaxf(m, __shfl_xor_sync(0xffffffffu, m, s));
        const float e = __expf(logit - m);
        float ssum = e;
#pragma unroll
        for (int s = 16; s > 0; s >>= 1) ssum += __shfl_xor_sync(0xffffffffu, ssum, s);
        const float wgt = e / ssum;

        const float ox = off[(((size_t)nq * NH + h) * 32 + j) * 2 + 0];
        const float oy = off[(((size_t)nq * NH + h) * 32 + j) * 2 + 1];

        const int l = j >> 3;
        const int z = j & 3;
        const float rx = ref[((size_t)nq * NZ + z) * 2 + 0];
        const float ry = ref[((size_t)nq * NZ + z) * 2 + 1];

        const int   hl = c_H[l];
        const int   wl = c_W[l];
        const int   st = c_ST[l];
        const float fhl = (float)hl;
        const float fwl = (float)wl;

        const float x = (rx + __fdividef(ox, fwl)) * fwl - 0.5f;
        const float y = (ry + __fdividef(oy, fhl)) * fhl - 0.5f;

        const float x0f = floorf(x);
        const float y0f = floorf(y);
        const float wx = x - x0f;
        const float wy = y - y0f;
        const int x0 = (int)x0f, y0 = (int)y0f;
        const int x1 = x0 + 1,   y1 = y0 + 1;

        const bool vx0 = (x0 >= 0) & (x0 < wl);
        const bool vx1 = (x1 >= 0) & (x1 < wl);
        const bool vy0 = (y0 >= 0) & (y0 < hl);
        const bool vy1 = (y1 >= 0) & (y1 < hl);

        const bool v00 = vx0 & vy0, v10 = vx1 & vy0;
        const bool v01 = vx0 & vy1, v11 = vx1 & vy1;

        int4 a;
        a.x = v00 ? (st + y0 * wl + x0) * DM : 0;
        a.y = v10 ? (st + y0 * wl + x1) * DM : 0;
        a.z = v01 ? (st + y1 * wl + x0) * DM : 0;
        a.w = v11 ? (st + y1 * wl + x1) * DM : 0;

        float4 w4;
        w4.x = v00 ? wgt * (1.f - wx) * (1.f - wy) : 0.f;
        w4.y = v10 ? wgt * wx * (1.f - wy)         : 0.f;
        w4.z = v01 ? wgt * (1.f - wx) * wy         : 0.f;
        w4.w = v11 ? wgt * wx * wy                 : 0.f;

        s_addr[t] = a;
        s_w[t]    = w4;
    }
    __syncthreads();

    const float* __restrict__ vb =
        value + (size_t)n * LEN_IN * DM + h * DH + j;

    float acc = 0.f;
#pragma unroll 8
    for (int s = 0; s < 32; s++) {
        const int4   a  = s_addr[h * 32 + s];
        const float4 w4 = s_w[h * 32 + s];
        acc += w4.x * __ldg(vb + a.x);
        acc += w4.y * __ldg(vb + a.y);
        acc += w4.z * __ldg(vb + a.z);
        acc += w4.w * __ldg(vb + a.w);
    }

    out[(size_t)nq * DM + h * DH + j] = acc;
}

// ---------------- launch ----------------------------------------------------
extern "C" void kernel_launch(void* const* d_in, const int* in_sizes, int n_in,
                              void* d_out, int out_size) {
    const float* query  = (const float*)d_in[0];
    const float* refpts = (const float*)d_in[2];
    const float* inflat = (const float*)d_in[3];
    const float* bv = (const float*)d_in[7];
    const float* Wv = (const float*)d_in[6];
    const float* Wo = (const float*)d_in[8];
    const float* bo = (const float*)d_in[9];
    const float* Wa = (const float*)d_in[10];
    const float* ba = (const float*)d_in[11];
    float* out = (float*)d_out;

    float *valuep, *offp, *awlp;
    cudaGetSymbolAddress((void**)&valuep, g_value);
    cudaGetSymbolAddress((void**)&offp,   g_off);
    cudaGetSymbolAddress((void**)&awlp,   g_awl);

    __nv_bfloat16 *vhi, *vlo, *qhi, *qlo, *wvhi, *wvlo, *wohi, *wolo, *wahi, *walo;
    cudaGetSymbolAddress((void**)&vhi,  g_vhi);
    cudaGetSymbolAddress((void**)&vlo,  g_vlo);
    cudaGetSymbolAddress((void**)&qhi,  g_qhi);
    cudaGetSymbolAddress((void**)&qlo,  g_qlo);
    cudaGetSymbolAddress((void**)&wvhi, g_wvhi);
    cudaGetSymbolAddress((void**)&wvlo, g_wvlo);
    cudaGetSymbolAddress((void**)&wohi, g_wohi);
    cudaGetSymbolAddress((void**)&wolo, g_wolo);
    cudaGetSymbolAddress((void**)&wahi, g_wahi);
    cudaGetSymbolAddress((void**)&walo, g_walo);

    cudaFuncSetAttribute(gemm_split3_kernel,
                         cudaFuncAttributeMaxDynamicSharedMemorySize, SMEM_BYTES);

    const int Mv = NB * LEN_IN;   // 119680
    const int Mq = NB * LQ;       // 20000

    // split passes
    {
        int n4 = Mv * KDIM / 4;
        split_kernel<<<(n4 + 255) / 256, 256>>>(inflat, vhi, vlo, n4);
    }
    {
        int n4 = Mq * KDIM / 4;
        split_kernel<<<(n4 + 255) / 256, 256>>>(query, qhi, qlo, n4);
    }
    {
        int n4 = KDIM * 256 / 4;
        split_kernel<<<(n4 + 255) / 256, 256>>>(Wv, wvhi, wvlo, n4);
        split_kernel<<<(KDIM * 512 / 4 + 255) / 256, 256>>>(Wo, wohi, wolo, KDIM * 512 / 4);
        split_kernel<<<(n4 + 255) / 256, 256>>>(Wa, wahi, walo, n4);
    }

    // GEMMs
    {
        dim3 grid(256 / BN, Mv / BM);   // 4 x 935
        gemm_split3_kernel<<<grid, 256, SMEM_BYTES>>>(vhi, vlo, wvhi, wvlo, bv, valuep, Mv, 256);
    }
    {
        dim3 grid(512 / BN, (Mq + BM - 1) / BM);  // 8 x 157
        gemm_split3_kernel<<<grid, 256, SMEM_BYTES>>>(qhi, qlo, wohi, wolo, bo, offp, Mq, 512);
    }
    {
        dim3 grid(256 / BN, (Mq + BM - 1) / BM);  // 4 x 157
        gemm_split3_kernel<<<grid, 256, SMEM_BYTES>>>(qhi, qlo, wahi, walo, ba, awlp, Mq, 256);
    }

    msda_sample_kernel<<<Mq, 256>>>(refpts, offp, awlp, valuep, out);
}